// round 2
// baseline (speedup 1.0000x reference)
#include <cuda_runtime.h>

// SpikingCell recurrence, simplified (see R1):
//   clamp gate always-true -> dropped; spike counter unused -> dropped
//   per (b,n):  v += (refrac>=2) ? x[t-1] : 0 ; out=(v>=1); v-=out;
//               refrac = out ? 0 : refrac+1
// Pure streaming: 128MB in, 128MB out. DRAM-bound.
//
// R2 change: scalar (1 float / thread) instead of float4/thread.
//   131072 threads = 512 blocks x 256 -> ~3.5 blocks/SM, 24-32 warps/SM
//   (vs 128 blocks / 8 warps/SM in R1, which left 20 SMs idle and exposed
//   DRAM latency on the serial t-dependency). Streaming cache hints since
//   256MB can't live in L2 anyway.

constexpr int B = 16, T = 256, N = 8192;
constexpr int THREADS = 256;
constexpr int GRID = (B * N) / THREADS;   // 512 blocks

__global__ __launch_bounds__(THREADS) void spiking_kernel(
    const float* __restrict__ x, float* __restrict__ out)
{
    int tid = blockIdx.x * THREADS + threadIdx.x;   // 0 .. B*N-1
    int b = tid >> 13;            // / N
    int n = tid & (N - 1);        // % N
    size_t base = (size_t)b * T * N + n;

    const float* __restrict__ xp = x + base;
    float* __restrict__ op = out + base;

    float v = 0.f;   // membrane potential
    int   r = 0;     // refractory counter
    float d = 0.f;   // dv buffer (x[t-1])

#pragma unroll 8
    for (int t = 0; t < T; t++) {
        // evict-streaming load; independent of recurrence so the unroll
        // front-batches 8 of these per warp for DRAM MLP.
        float xt = __ldcs(xp); xp += N;

        v += (r >= 2) ? d : 0.f;
        float o = (v >= 1.f) ? 1.f : 0.f;
        v -= o;
        r = (o != 0.f) ? 0 : (r + 1);

        __stcs(op, o); op += N;

        d = xt;
    }
}

extern "C" void kernel_launch(void* const* d_in, const int* in_sizes, int n_in,
                              void* d_out, int out_size)
{
    const float* x = (const float*)d_in[0];
    float* out = (float*)d_out;
    spiking_kernel<<<GRID, THREADS>>>(x, out);
}

// round 3
// speedup vs baseline: 1.7531x; 1.7531x over previous
#include <cuda_runtime.h>

// SpikingCell recurrence, simplified (see R1):
//   clamp gate always-true -> dropped; spike counter unused -> dropped
//   per (b,n):  v += (refrac>=2) ? x[t-1] : 0 ; out=(v>=1); v-=out;
//               refrac = out ? 0 : refrac+1
// Pure streaming: 128MB in, 128MB out. DRAM-bound; goal = keep >=15KB/SM of
// loads in flight (46GB/s/SM x ~320ns DRAM latency).
//
// R3: explicit double-buffered pipeline (depth 8) so MLP is structural, not
// at ptxas's mercy (R1 regs=34 proved it only kept ~2 loads in flight).
// 1024 blocks x 128 threads -> 6.92 blocks/SM, ~1% wave imbalance
// (vs 15% for the 512/128-block configs of R1/R2).

constexpr int B = 16, T = 256, N = 8192;
constexpr int THREADS = 128;
constexpr int GRID = (B * N) / THREADS;   // 1024 blocks
constexpr int PF = 8;                     // pipeline depth
constexpr int NBATCH = T / PF;            // 32

__global__ __launch_bounds__(THREADS) void spiking_kernel(
    const float* __restrict__ x, float* __restrict__ out)
{
    int tid = blockIdx.x * THREADS + threadIdx.x;   // 0 .. B*N-1
    int b = tid >> 13;            // / N
    int n = tid & (N - 1);        // % N
    size_t base = (size_t)b * T * N + n;

    const float* __restrict__ xp = x + base;
    float* __restrict__ op = out + base;

    float v = 0.f;   // membrane potential
    int   r = 0;     // refractory counter
    float d = 0.f;   // dv buffer (x[t-1])

    float cur[PF];

    // prologue: fill first batch
#pragma unroll
    for (int i = 0; i < PF; i++) cur[i] = __ldcs(xp + (size_t)i * N);
    xp += (size_t)PF * N;

    for (int batch = 0; batch < NBATCH - 1; batch++) {
        // issue next batch's 8 loads up front (structural MLP=8/thread)
        float nxt[PF];
#pragma unroll
        for (int i = 0; i < PF; i++) nxt[i] = __ldcs(xp + (size_t)i * N);
        xp += (size_t)PF * N;

        // compute + store current batch while next batch is in flight
#pragma unroll
        for (int i = 0; i < PF; i++) {
            v += (r >= 2) ? d : 0.f;
            float o = (v >= 1.f) ? 1.f : 0.f;
            v -= o;
            r = (o != 0.f) ? 0 : (r + 1);
            __stcs(op, o); op += N;
            d = cur[i];
        }

#pragma unroll
        for (int i = 0; i < PF; i++) cur[i] = nxt[i];
    }

    // epilogue: last batch
#pragma unroll
    for (int i = 0; i < PF; i++) {
        v += (r >= 2) ? d : 0.f;
        float o = (v >= 1.f) ? 1.f : 0.f;
        v -= o;
        r = (o != 0.f) ? 0 : (r + 1);
        __stcs(op, o); op += N;
        d = cur[i];
    }
}

extern "C" void kernel_launch(void* const* d_in, const int* in_sizes, int n_in,
                              void* d_out, int out_size)
{
    const float* x = (const float*)d_in[0];
    float* out = (float*)d_out;
    spiking_kernel<<<GRID, THREADS>>>(x, out);
}

// round 4
// speedup vs baseline: 1.8057x; 1.0300x over previous
#include <cuda_runtime.h>

// SpikingCell recurrence, simplified (see R1):
//   clamp gate always-true -> dropped; spike counter unused -> dropped
//   per (b,n):  v += (refrac>=2) ? x[t-1] : 0 ; out=(v>=1); v-=out;
//               refrac = out ? 0 : refrac+1
// Pure streaming: 128MB in, 128MB out. DRAM-bound.
//
// R4: pipeline depth 8 -> 16 via ping-pong buffers (A/B), which also kills
// the cur<-nxt register copies of R3. In-flight loads/SM double to ~56KB,
// comfortably above the ~25KB needed at near-saturated DRAM latency.
// Grid stays 1024 x 128 (imbalance ~1%).

constexpr int B = 16, T = 256, N = 8192;
constexpr int THREADS = 128;
constexpr int GRID = (B * N) / THREADS;   // 1024 blocks
constexpr int PF = 16;                    // pipeline depth
constexpr int NBATCH = T / PF;            // 16 batches -> 8 ping-pong pairs

__global__ __launch_bounds__(THREADS) void spiking_kernel(
    const float* __restrict__ x, float* __restrict__ out)
{
    int tid = blockIdx.x * THREADS + threadIdx.x;   // 0 .. B*N-1
    int b = tid >> 13;            // / N
    int n = tid & (N - 1);        // % N
    size_t base = (size_t)b * T * N + n;

    const float* __restrict__ xp = x + base;
    float* __restrict__ op = out + base;

    float v = 0.f;   // membrane potential
    int   r = 0;     // refractory counter
    float d = 0.f;   // dv buffer (x[t-1])

    float bufA[PF], bufB[PF];

    // prologue: fill A
#pragma unroll
    for (int i = 0; i < PF; i++) bufA[i] = __ldcs(xp + (size_t)i * N);
    xp += (size_t)PF * N;

#pragma unroll 1
    for (int pair = 0; pair < NBATCH / 2 - 1; pair++) {
        // load B, compute A
#pragma unroll
        for (int i = 0; i < PF; i++) bufB[i] = __ldcs(xp + (size_t)i * N);
        xp += (size_t)PF * N;
#pragma unroll
        for (int i = 0; i < PF; i++) {
            v += (r >= 2) ? d : 0.f;
            float o = (v >= 1.f) ? 1.f : 0.f;
            v -= o;
            r = (o != 0.f) ? 0 : (r + 1);
            __stcs(op, o); op += N;
            d = bufA[i];
        }
        // load A, compute B
#pragma unroll
        for (int i = 0; i < PF; i++) bufA[i] = __ldcs(xp + (size_t)i * N);
        xp += (size_t)PF * N;
#pragma unroll
        for (int i = 0; i < PF; i++) {
            v += (r >= 2) ? d : 0.f;
            float o = (v >= 1.f) ? 1.f : 0.f;
            v -= o;
            r = (o != 0.f) ? 0 : (r + 1);
            __stcs(op, o); op += N;
            d = bufB[i];
        }
    }

    // tail: load final B, compute A, then compute B (no more loads)
#pragma unroll
    for (int i = 0; i < PF; i++) bufB[i] = __ldcs(xp + (size_t)i * N);
#pragma unroll
    for (int i = 0; i < PF; i++) {
        v += (r >= 2) ? d : 0.f;
        float o = (v >= 1.f) ? 1.f : 0.f;
        v -= o;
        r = (o != 0.f) ? 0 : (r + 1);
        __stcs(op, o); op += N;
        d = bufA[i];
    }
#pragma unroll
    for (int i = 0; i < PF; i++) {
        v += (r >= 2) ? d : 0.f;
        float o = (v >= 1.f) ? 1.f : 0.f;
        v -= o;
        r = (o != 0.f) ? 0 : (r + 1);
        __stcs(op, o); op += N;
        d = bufB[i];
    }
}

extern "C" void kernel_launch(void* const* d_in, const int* in_sizes, int n_in,
                              void* d_out, int out_size)
{
    const float* x = (const float*)d_in[0];
    float* out = (float*)d_out;
    spiking_kernel<<<GRID, THREADS>>>(x, out);
}

// round 5
// speedup vs baseline: 1.8146x; 1.0049x over previous
#include <cuda_runtime.h>

// SpikingCell recurrence, simplified (see R1):
//   clamp gate always-true -> dropped; spike counter unused -> dropped
//   per (b,n):  v += (refrac>=2) ? x[t-1] : 0 ; out=(v>=1); v-=out;
//               refrac = out ? 0 : refrac+1
// Pure streaming: 128MB in, 128MB out. DRAM-bound at ~71% with scalar
// accesses; R3->R4 showed in-flight depth is NOT the lever, so R5 targets
// DRAM transaction efficiency: float2 per thread (LDG.64/STG.64, 256B/warp),
// halving LSU ops per byte. Grid stays 1024 blocks (6.92/SM, ~1% imbalance);
// 64 threads/block -> 65536 threads, ~14 warps/SM, PF=8 float2 ping-pong
// keeps ~28KB/SM in flight (the proven-sufficient R3 level).

constexpr int B = 16, T = 256, N = 8192;
constexpr int N2 = N / 2;                  // float2 lanes per row = 4096
constexpr int THREADS = 64;
constexpr int GRID = (B * N2) / THREADS;   // 1024 blocks
constexpr int PF = 8;                      // pipeline depth (float2 steps)
constexpr int NBATCH = T / PF;             // 32 batches -> 16 ping-pong pairs

__device__ __forceinline__ void step(float2 d, float& v0, float& v1,
                                     int& r0, int& r1, float2& o)
{
    v0 += (r0 >= 2) ? d.x : 0.f;
    o.x = (v0 >= 1.f) ? 1.f : 0.f;
    v0 -= o.x;
    r0 = (o.x != 0.f) ? 0 : (r0 + 1);

    v1 += (r1 >= 2) ? d.y : 0.f;
    o.y = (v1 >= 1.f) ? 1.f : 0.f;
    v1 -= o.y;
    r1 = (o.y != 0.f) ? 0 : (r1 + 1);
}

__global__ __launch_bounds__(THREADS) void spiking_kernel(
    const float2* __restrict__ x, float2* __restrict__ out)
{
    int tid = blockIdx.x * THREADS + threadIdx.x;   // 0 .. B*N2-1
    int b = tid >> 12;            // / N2
    int c = tid & (N2 - 1);       // % N2
    size_t base = (size_t)b * T * N2 + c;

    const float2* __restrict__ xp = x + base;
    float2* __restrict__ op = out + base;

    float v0 = 0.f, v1 = 0.f;     // membrane potentials
    int   r0 = 0,   r1 = 0;       // refractory counters
    float2 d = make_float2(0.f, 0.f);   // dv buffer (x[t-1])

    float2 bufA[PF], bufB[PF];

    // prologue: fill A
#pragma unroll
    for (int i = 0; i < PF; i++) bufA[i] = __ldcs(xp + (size_t)i * N2);
    xp += (size_t)PF * N2;

#pragma unroll 1
    for (int pair = 0; pair < NBATCH / 2 - 1; pair++) {
        // load B, compute+store A
#pragma unroll
        for (int i = 0; i < PF; i++) bufB[i] = __ldcs(xp + (size_t)i * N2);
        xp += (size_t)PF * N2;
#pragma unroll
        for (int i = 0; i < PF; i++) {
            float2 o;
            step(d, v0, v1, r0, r1, o);
            __stcs(op, o); op += N2;
            d = bufA[i];
        }
        // load A, compute+store B
#pragma unroll
        for (int i = 0; i < PF; i++) bufA[i] = __ldcs(xp + (size_t)i * N2);
        xp += (size_t)PF * N2;
#pragma unroll
        for (int i = 0; i < PF; i++) {
            float2 o;
            step(d, v0, v1, r0, r1, o);
            __stcs(op, o); op += N2;
            d = bufB[i];
        }
    }

    // tail: load final B, compute A, then compute B
#pragma unroll
    for (int i = 0; i < PF; i++) bufB[i] = __ldcs(xp + (size_t)i * N2);
#pragma unroll
    for (int i = 0; i < PF; i++) {
        float2 o;
        step(d, v0, v1, r0, r1, o);
        __stcs(op, o); op += N2;
        d = bufA[i];
    }
#pragma unroll
    for (int i = 0; i < PF; i++) {
        float2 o;
        step(d, v0, v1, r0, r1, o);
        __stcs(op, o); op += N2;
        d = bufB[i];
    }
}

extern "C" void kernel_launch(void* const* d_in, const int* in_sizes, int n_in,
                              void* d_out, int out_size)
{
    const float2* x = (const float2*)d_in[0];
    float2* out = (float2*)d_out;
    spiking_kernel<<<GRID, THREADS>>>(x, out);
}